// round 1
// baseline (speedup 1.0000x reference)
#include <cuda_runtime.h>
#include <cstdint>

// Problem constants
#define T_SEQ     4096
#define D_MODEL   1024
#define NUM_HEADS 16
#define HEAD_DIM  64   // D_MODEL / NUM_HEADS

// ---------------------------------------------------------------------------
// Scratch (no cudaMalloc allowed): Q, K, V, attention output, each [T, D] fp32
// ---------------------------------------------------------------------------
__device__ float g_Q[T_SEQ * D_MODEL];
__device__ float g_K[T_SEQ * D_MODEL];
__device__ float g_V[T_SEQ * D_MODEL];
__device__ float g_O[T_SEQ * D_MODEL];

// ---------------------------------------------------------------------------
// SGEMM core: C[M,N] = A[M,K] @ B[N,K]^T   (torch Linear: y = x @ W.T)
// BM=BN=128, BK=16, 256 threads, 8x8 per thread, smem tiles stored k-major
// transposed for conflict-light compute reads.
// ---------------------------------------------------------------------------
#define GM 4096   // only used for qkv/out wrappers; body takes M,N,K
#define BK_PAD 132

__device__ __forceinline__ void sgemm_body(
    const float* __restrict__ A, const float* __restrict__ B,
    float* __restrict__ C, int M, int N, int K)
{
    __shared__ float As[16][BK_PAD];
    __shared__ float Bs[16][BK_PAD];

    const int tid = threadIdx.x;
    const int tx  = tid & 15;    // n sub-tile
    const int ty  = tid >> 4;    // m sub-tile
    const int m0  = blockIdx.y * 128;
    const int n0  = blockIdx.x * 128;
    const int lrow = tid >> 2;          // 0..63
    const int lk   = (tid & 3) * 4;     // 0,4,8,12

    float acc[8][8];
    #pragma unroll
    for (int i = 0; i < 8; i++)
        #pragma unroll
        for (int j = 0; j < 8; j++) acc[i][j] = 0.f;

    for (int k0 = 0; k0 < K; k0 += 16) {
        // Load 128x16 tiles of A and B (K contiguous in gmem), store transposed.
        #pragma unroll
        for (int i = 0; i < 2; i++) {
            const int row = lrow + i * 64;
            float4 a = *reinterpret_cast<const float4*>(&A[(size_t)(m0 + row) * K + k0 + lk]);
            As[lk + 0][row] = a.x; As[lk + 1][row] = a.y;
            As[lk + 2][row] = a.z; As[lk + 3][row] = a.w;
            float4 b = *reinterpret_cast<const float4*>(&B[(size_t)(n0 + row) * K + k0 + lk]);
            Bs[lk + 0][row] = b.x; Bs[lk + 1][row] = b.y;
            Bs[lk + 2][row] = b.z; Bs[lk + 3][row] = b.w;
        }
        __syncthreads();

        #pragma unroll
        for (int k = 0; k < 16; k++) {
            float a[8], b[8];
            *reinterpret_cast<float4*>(&a[0]) = *reinterpret_cast<const float4*>(&As[k][ty * 8]);
            *reinterpret_cast<float4*>(&a[4]) = *reinterpret_cast<const float4*>(&As[k][ty * 8 + 4]);
            *reinterpret_cast<float4*>(&b[0]) = *reinterpret_cast<const float4*>(&Bs[k][tx * 8]);
            *reinterpret_cast<float4*>(&b[4]) = *reinterpret_cast<const float4*>(&Bs[k][tx * 8 + 4]);
            #pragma unroll
            for (int i = 0; i < 8; i++)
                #pragma unroll
                for (int j = 0; j < 8; j++)
                    acc[i][j] += a[i] * b[j];
        }
        __syncthreads();
    }

    #pragma unroll
    for (int i = 0; i < 8; i++) {
        float* crow = &C[(size_t)(m0 + ty * 8 + i) * N + n0 + tx * 8];
        *reinterpret_cast<float4*>(&crow[0]) =
            make_float4(acc[i][0], acc[i][1], acc[i][2], acc[i][3]);
        *reinterpret_cast<float4*>(&crow[4]) =
            make_float4(acc[i][4], acc[i][5], acc[i][6], acc[i][7]);
    }
}

// QKV fused over blockIdx.z: z=0 -> Q, z=1 -> K, z=2 -> V
__global__ __launch_bounds__(256) void qkv_gemm(
    const float* __restrict__ x,
    const float* __restrict__ Wq,
    const float* __restrict__ Wk,
    const float* __restrict__ Wv)
{
    const float* B = (blockIdx.z == 0) ? Wq : (blockIdx.z == 1) ? Wk : Wv;
    float*       C = (blockIdx.z == 0) ? g_Q : (blockIdx.z == 1) ? g_K : g_V;
    sgemm_body(x, B, C, T_SEQ, D_MODEL, D_MODEL);
}

__global__ __launch_bounds__(256) void out_gemm(
    const float* __restrict__ Wo, float* __restrict__ out)
{
    sgemm_body(g_O, Wo, out, T_SEQ, D_MODEL, D_MODEL);
}

// ---------------------------------------------------------------------------
// Causal flash attention, fp32.
// Grid: (T/64, NUM_HEADS), 256 threads.
// BQ = 64 query rows per block; 4 threads per row (c = tid&3).
// Key tiles of 32. Each thread:
//   - holds its full Q row (64 floats) in registers
//   - computes 8 scores per tile (j = jj*4 + c, interleaved for bank spread)
//   - online softmax state (m, l) shared across the quad via shfl
//   - accumulates output dims [c*16, c*16+16)
// P is staged via smem (per-warp-private rows -> __syncwarp only).
// ---------------------------------------------------------------------------
#define KV_STRIDE 68
#define PS_STRIDE 36

__global__ __launch_bounds__(256) void flash_attn()
{
    __shared__ float Ks[32][KV_STRIDE];
    __shared__ float Vs[32][KV_STRIDE];
    __shared__ float Ps[64][PS_STRIDE];

    const int tid = threadIdx.x;
    const int qt  = (int)gridDim.x - 1 - (int)blockIdx.x;  // heavy tiles first
    const int h   = blockIdx.y;
    const int r   = tid >> 2;        // query row in tile (0..63)
    const int c   = tid & 3;         // quarter index
    const int row_g = qt * 64 + r;
    const float scale = 0.125f;      // 1/sqrt(64)

    // Q row in registers (redundant across the quad; L1-broadcast)
    float4 q4[16];
    const float4* Qrow =
        reinterpret_cast<const float4*>(&g_Q[(size_t)row_g * D_MODEL + h * HEAD_DIM]);
    #pragma unroll
    for (int i = 0; i < 16; i++) q4[i] = Qrow[i];

    float m = -1e30f, l = 0.f;
    float4 acc[4];
    #pragma unroll
    for (int i = 0; i < 4; i++) acc[i] = make_float4(0.f, 0.f, 0.f, 0.f);

    const int jt_max = 2 * qt + 1;   // keys up to qt*64+63
    for (int jt = 0; jt <= jt_max; jt++) {
        const int j0 = jt * 32;
        // Load K/V tiles: 32 rows x 64 cols -> 512 float4, 2 per thread.
        #pragma unroll
        for (int i = 0; i < 2; i++) {
            const int idx = tid + i * 256;
            const int jr  = idx >> 4;        // 0..31
            const int dq  = (idx & 15) * 4;  // 0..60
            *reinterpret_cast<float4*>(&Ks[jr][dq]) =
                *reinterpret_cast<const float4*>(
                    &g_K[(size_t)(j0 + jr) * D_MODEL + h * HEAD_DIM + dq]);
            *reinterpret_cast<float4*>(&Vs[jr][dq]) =
                *reinterpret_cast<const float4*>(
                    &g_V[(size_t)(j0 + jr) * D_MODEL + h * HEAD_DIM + dq]);
        }
        __syncthreads();

        // Phase A: scores for this thread's 8 keys (j = jj*4 + c)
        float s[8];
        #pragma unroll
        for (int jj = 0; jj < 8; jj++) s[jj] = 0.f;
        #pragma unroll
        for (int kq = 0; kq < 16; kq++) {
            const float4 qv = q4[kq];
            #pragma unroll
            for (int jj = 0; jj < 8; jj++) {
                const float4 kv = *reinterpret_cast<const float4*>(&Ks[jj * 4 + c][kq * 4]);
                s[jj] += qv.x * kv.x + qv.y * kv.y + qv.z * kv.z + qv.w * kv.w;
            }
        }

        // Mask + scale + local max
        float mloc = -1e30f;
        #pragma unroll
        for (int jj = 0; jj < 8; jj++) {
            const int jg = j0 + jj * 4 + c;
            const float sv = (jg <= row_g) ? s[jj] * scale : -1e30f;
            s[jj] = sv;
            mloc = fmaxf(mloc, sv);
        }
        // Quad (row) reduction of max
        mloc = fmaxf(mloc, __shfl_xor_sync(0xffffffffu, mloc, 1));
        mloc = fmaxf(mloc, __shfl_xor_sync(0xffffffffu, mloc, 2));

        const float mnew  = fmaxf(m, mloc);
        const float alpha = __expf(m - mnew);

        float psum = 0.f;
        #pragma unroll
        for (int jj = 0; jj < 8; jj++) {
            const float p = __expf(s[jj] - mnew);
            Ps[r][jj * 4 + c] = p;
            psum += p;
        }
        psum += __shfl_xor_sync(0xffffffffu, psum, 1);
        psum += __shfl_xor_sync(0xffffffffu, psum, 2);

        l = l * alpha + psum;
        m = mnew;
        #pragma unroll
        for (int i = 0; i < 4; i++) {
            acc[i].x *= alpha; acc[i].y *= alpha;
            acc[i].z *= alpha; acc[i].w *= alpha;
        }

        __syncwarp();  // Ps rows are written and read within the same warp

        // Phase B: acc += P @ V for this thread's 16 output dims
        #pragma unroll 8
        for (int j = 0; j < 32; j++) {
            const float pj = Ps[r][j];
            const float4* vrow = reinterpret_cast<const float4*>(&Vs[j][c * 16]);
            #pragma unroll
            for (int dd = 0; dd < 4; dd++) {
                const float4 v = vrow[dd];
                acc[dd].x += pj * v.x; acc[dd].y += pj * v.y;
                acc[dd].z += pj * v.z; acc[dd].w += pj * v.w;
            }
        }
        __syncthreads();  // before next tile overwrites Ks/Vs
    }

    const float inv = 1.0f / l;
    float4* Orow = reinterpret_cast<float4*>(
        &g_O[(size_t)row_g * D_MODEL + h * HEAD_DIM + c * 16]);
    #pragma unroll
    for (int dd = 0; dd < 4; dd++) {
        float4 o = acc[dd];
        o.x *= inv; o.y *= inv; o.z *= inv; o.w *= inv;
        Orow[dd] = o;
    }
}

// ---------------------------------------------------------------------------
// Launch: QKV projections -> flash attention -> output projection
// ---------------------------------------------------------------------------
extern "C" void kernel_launch(void* const* d_in, const int* in_sizes, int n_in,
                              void* d_out, int out_size)
{
    (void)in_sizes; (void)n_in; (void)out_size;
    const float* x  = (const float*)d_in[0];
    const float* Wq = (const float*)d_in[1];
    const float* Wk = (const float*)d_in[2];
    const float* Wv = (const float*)d_in[3];
    const float* Wo = (const float*)d_in[4];
    float* out = (float*)d_out;

    dim3 gproj(D_MODEL / 128, T_SEQ / 128, 3);   // (8, 32, 3)
    qkv_gemm<<<gproj, 256>>>(x, Wq, Wk, Wv);

    dim3 gattn(T_SEQ / 64, NUM_HEADS);           // (64, 16)
    flash_attn<<<gattn, 256>>>();

    dim3 gout(D_MODEL / 128, T_SEQ / 128, 1);    // (8, 32)
    out_gemm<<<gout, 256>>>(Wo, out);
}

// round 2
// speedup vs baseline: 5.3206x; 5.3206x over previous
#include <cuda_runtime.h>
#include <cstdint>

// Problem constants
#define T_SEQ     4096
#define D_MODEL   1024
#define NUM_HEADS 16
#define HEAD_DIM  64

// ---------------------------------------------------------------------------
// Scratch: Q, K, V, attention output, each [T, D] fp32 (no cudaMalloc allowed)
// ---------------------------------------------------------------------------
__device__ float g_Q[T_SEQ * D_MODEL];
__device__ float g_K[T_SEQ * D_MODEL];
__device__ float g_V[T_SEQ * D_MODEL];
__device__ float g_O[T_SEQ * D_MODEL];

// ---------------------------------------------------------------------------
// tf32 helpers
// ---------------------------------------------------------------------------
__device__ __forceinline__ uint32_t f2tf(float f) {
    uint32_t u;
    asm("cvt.rna.tf32.f32 %0, %1;" : "=r"(u) : "f"(f));
    return u;
}

// D = A@B + C, m16n8k8, A row-major (m x k), B col-major (k x n), fp32 acc.
__device__ __forceinline__ void mma_tf32(float4& c, const uint32_t a[4],
                                         uint32_t b0, uint32_t b1) {
    asm volatile(
        "mma.sync.aligned.m16n8k8.row.col.f32.tf32.tf32.f32 "
        "{%0,%1,%2,%3}, {%4,%5,%6,%7}, {%8,%9}, {%10,%11,%12,%13};\n"
        : "=f"(c.x), "=f"(c.y), "=f"(c.z), "=f"(c.w)
        : "r"(a[0]), "r"(a[1]), "r"(a[2]), "r"(a[3]),
          "r"(b0), "r"(b1),
          "f"(c.x), "f"(c.y), "f"(c.z), "f"(c.w));
}

// ---------------------------------------------------------------------------
// tf32 GEMM: C[M,N] = A[M,K] @ B[N,K]^T   (torch Linear)
// 256 threads = 8 warps (2m x 4n), BM=BN=128, BK=32.
// Smem tiles stored [row][k] with pad 36 -> fragment reads conflict-free
// (bank = (4*g + tig) % 32, all 32 lanes distinct).
// ---------------------------------------------------------------------------
__device__ __forceinline__ void gemm_tf32_body(
    const float* __restrict__ A, const float* __restrict__ B,
    float* __restrict__ C, int M, int N, int K)
{
    __shared__ __align__(16) uint32_t As[128][36];
    __shared__ __align__(16) uint32_t Bs[128][36];

    const int tid  = threadIdx.x;
    const int lane = tid & 31;
    const int wid  = tid >> 5;
    const int g    = lane >> 2;   // group of 4
    const int tig  = lane & 3;    // thread in group
    const int wm   = wid >> 2;    // 0..1
    const int wn   = wid & 3;     // 0..3
    const int m0   = blockIdx.y * 128;
    const int n0   = blockIdx.x * 128;
    const int mb   = wm * 64;
    const int nb   = wn * 32;

    float4 acc[4][4];
    #pragma unroll
    for (int i = 0; i < 4; i++)
        #pragma unroll
        for (int j = 0; j < 4; j++) acc[i][j] = make_float4(0.f, 0.f, 0.f, 0.f);

    for (int k0 = 0; k0 < K; k0 += 32) {
        // Load 128x32 A and B tiles, cvt to tf32 at store.
        #pragma unroll
        for (int i = 0; i < 4; i++) {
            const int id  = tid + i * 256;
            const int row = id >> 3;
            const int k4  = (id & 7) * 4;
            float4 a = *reinterpret_cast<const float4*>(
                &A[(size_t)(m0 + row) * K + k0 + k4]);
            uint4 av = make_uint4(f2tf(a.x), f2tf(a.y), f2tf(a.z), f2tf(a.w));
            *reinterpret_cast<uint4*>(&As[row][k4]) = av;
            float4 b = *reinterpret_cast<const float4*>(
                &B[(size_t)(n0 + row) * K + k0 + k4]);
            uint4 bv = make_uint4(f2tf(b.x), f2tf(b.y), f2tf(b.z), f2tf(b.w));
            *reinterpret_cast<uint4*>(&Bs[row][k4]) = bv;
        }
        __syncthreads();

        #pragma unroll
        for (int ks = 0; ks < 4; ks++) {
            const int kk = ks * 8;
            uint32_t af[4][4], bf[4][2];
            #pragma unroll
            for (int mt = 0; mt < 4; mt++) {
                const int m = mb + mt * 16;
                af[mt][0] = As[m + g    ][kk + tig];
                af[mt][1] = As[m + g + 8][kk + tig];
                af[mt][2] = As[m + g    ][kk + tig + 4];
                af[mt][3] = As[m + g + 8][kk + tig + 4];
            }
            #pragma unroll
            for (int nt = 0; nt < 4; nt++) {
                const int n = nb + nt * 8 + g;
                bf[nt][0] = Bs[n][kk + tig];
                bf[nt][1] = Bs[n][kk + tig + 4];
            }
            #pragma unroll
            for (int mt = 0; mt < 4; mt++)
                #pragma unroll
                for (int nt = 0; nt < 4; nt++)
                    mma_tf32(acc[mt][nt], af[mt], bf[nt][0], bf[nt][1]);
        }
        __syncthreads();
    }

    // Epilogue: C fragment (g,2tig),(g,2tig+1),(g+8,2tig),(g+8,2tig+1)
    #pragma unroll
    for (int mt = 0; mt < 4; mt++) {
        const int row0 = m0 + mb + mt * 16 + g;
        #pragma unroll
        for (int nt = 0; nt < 4; nt++) {
            const int col = n0 + nb + nt * 8 + 2 * tig;
            *reinterpret_cast<float2*>(&C[(size_t)row0 * N + col]) =
                make_float2(acc[mt][nt].x, acc[mt][nt].y);
            *reinterpret_cast<float2*>(&C[(size_t)(row0 + 8) * N + col]) =
                make_float2(acc[mt][nt].z, acc[mt][nt].w);
        }
    }
}

__global__ __launch_bounds__(256) void qkv_gemm_tc(
    const float* __restrict__ x,
    const float* __restrict__ Wq,
    const float* __restrict__ Wk,
    const float* __restrict__ Wv)
{
    const float* B = (blockIdx.z == 0) ? Wq : (blockIdx.z == 1) ? Wk : Wv;
    float*       C = (blockIdx.z == 0) ? g_Q : (blockIdx.z == 1) ? g_K : g_V;
    gemm_tf32_body(x, B, C, T_SEQ, D_MODEL, D_MODEL);
}

__global__ __launch_bounds__(256) void out_gemm_tc(
    const float* __restrict__ Wo, float* __restrict__ out)
{
    gemm_tf32_body(g_O, Wo, out, T_SEQ, D_MODEL, D_MODEL);
}

// ---------------------------------------------------------------------------
// Causal flash attention, tf32 tensor cores.
// Grid (T/64, H), 128 threads = 4 warps; warp w owns query rows q0+16w..+15.
// KV tiles of 32. Q fragments register-resident for the whole KV loop.
// Vt layout: idx(d,s) = d*33 + 8*s  -> bank (d + 8s)%32:
//   b-frag loads (d=nb+g, s=kk+tig): g + 8*tig -> 32 distinct banks, 0 conflicts
//   transpose stores (same s, d=2*lane): 2-way only.
// P staged through per-warp smem to re-fragment C -> A (tf32-converted).
// ---------------------------------------------------------------------------
#define VT_IDX(d, s) ((d) * 33 + (s) * 8)

__global__ __launch_bounds__(128) void flash_attn_tc()
{
    __shared__ __align__(16) uint32_t Ks[32][68];
    __shared__ __align__(16) uint32_t Vt[2336];
    __shared__ __align__(16) uint32_t Ps[4][16][36];

    const int tid  = threadIdx.x;
    const int lane = tid & 31;
    const int w    = tid >> 5;
    const int g    = lane >> 2;
    const int tig  = lane & 3;
    const int qt   = (int)gridDim.x - 1 - (int)blockIdx.x;  // heavy first
    const int h    = blockIdx.y;
    const int q0   = qt * 64;
    const int r0   = q0 + w * 16 + g;
    const int r1   = r0 + 8;
    const float sc = 0.125f;  // 1/sqrt(64)

    // Q fragments (once per block)
    uint32_t qf[8][4];
    const float* Qb = g_Q + (size_t)h * HEAD_DIM;
    #pragma unroll
    for (int ks = 0; ks < 8; ks++) {
        const int k = ks * 8;
        qf[ks][0] = f2tf(Qb[(size_t)r0 * D_MODEL + k + tig]);
        qf[ks][1] = f2tf(Qb[(size_t)r1 * D_MODEL + k + tig]);
        qf[ks][2] = f2tf(Qb[(size_t)r0 * D_MODEL + k + tig + 4]);
        qf[ks][3] = f2tf(Qb[(size_t)r1 * D_MODEL + k + tig + 4]);
    }

    float m0v = -1e30f, m1v = -1e30f, l0 = 0.f, l1 = 0.f;
    float4 o[8];
    #pragma unroll
    for (int i = 0; i < 8; i++) o[i] = make_float4(0.f, 0.f, 0.f, 0.f);

    const int ntiles = 2 * qt + 2;
    for (int jt = 0; jt < ntiles; jt++) {
        const int j0 = jt * 32;

        // K tile: 32 x 64, float4 loads, cvt, row-major smem
        #pragma unroll
        for (int i = 0; i < 4; i++) {
            const int id = tid + i * 128;
            const int s  = id >> 4;
            const int c4 = (id & 15) * 4;
            float4 kv = *reinterpret_cast<const float4*>(
                &g_K[(size_t)(j0 + s) * D_MODEL + h * HEAD_DIM + c4]);
            *reinterpret_cast<uint4*>(&Ks[s][c4]) =
                make_uint4(f2tf(kv.x), f2tf(kv.y), f2tf(kv.z), f2tf(kv.w));
        }
        // V tile transposed: float2 loads (all lanes same s), scattered stores
        #pragma unroll
        for (int i = 0; i < 8; i++) {
            const int id = tid + i * 128;
            const int s  = id >> 5;
            const int d2 = (id & 31) * 2;
            float2 vv = *reinterpret_cast<const float2*>(
                &g_V[(size_t)(j0 + s) * D_MODEL + h * HEAD_DIM + d2]);
            Vt[VT_IDX(d2    , s)] = f2tf(vv.x);
            Vt[VT_IDX(d2 + 1, s)] = f2tf(vv.y);
        }
        __syncthreads();

        // S = Q K^T (16 x 32 per warp): 4 n-tiles x 8 k-steps
        float4 sa[4];
        #pragma unroll
        for (int nt = 0; nt < 4; nt++) sa[nt] = make_float4(0.f, 0.f, 0.f, 0.f);
        #pragma unroll
        for (int nt = 0; nt < 4; nt++) {
            const int n = nt * 8 + g;
            #pragma unroll
            for (int ks = 0; ks < 8; ks++) {
                const uint32_t b0 = Ks[n][ks * 8 + tig];
                const uint32_t b1 = Ks[n][ks * 8 + tig + 4];
                mma_tf32(sa[nt], qf[ks], b0, b1);
            }
        }

        // Mask + scale + row maxima
        float mx0 = -1e30f, mx1 = -1e30f;
        #pragma unroll
        for (int nt = 0; nt < 4; nt++) {
            const int c0 = j0 + nt * 8 + 2 * tig;
            sa[nt].x = (c0     <= r0) ? sa[nt].x * sc : -1e30f;
            sa[nt].y = (c0 + 1 <= r0) ? sa[nt].y * sc : -1e30f;
            sa[nt].z = (c0     <= r1) ? sa[nt].z * sc : -1e30f;
            sa[nt].w = (c0 + 1 <= r1) ? sa[nt].w * sc : -1e30f;
            mx0 = fmaxf(mx0, fmaxf(sa[nt].x, sa[nt].y));
            mx1 = fmaxf(mx1, fmaxf(sa[nt].z, sa[nt].w));
        }
        mx0 = fmaxf(mx0, __shfl_xor_sync(0xffffffffu, mx0, 1));
        mx0 = fmaxf(mx0, __shfl_xor_sync(0xffffffffu, mx0, 2));
        mx1 = fmaxf(mx1, __shfl_xor_sync(0xffffffffu, mx1, 1));
        mx1 = fmaxf(mx1, __shfl_xor_sync(0xffffffffu, mx1, 2));

        const float mn0 = fmaxf(m0v, mx0);
        const float mn1 = fmaxf(m1v, mx1);
        const float al0 = __expf(m0v - mn0);
        const float al1 = __expf(m1v - mn1);

        float ps0 = 0.f, ps1 = 0.f;
        #pragma unroll
        for (int nt = 0; nt < 4; nt++) {
            const float px = __expf(sa[nt].x - mn0);
            const float py = __expf(sa[nt].y - mn0);
            const float pz = __expf(sa[nt].z - mn1);
            const float pw = __expf(sa[nt].w - mn1);
            ps0 += px + py;
            ps1 += pz + pw;
            const int c = nt * 8 + 2 * tig;
            *reinterpret_cast<uint2*>(&Ps[w][g    ][c]) = make_uint2(f2tf(px), f2tf(py));
            *reinterpret_cast<uint2*>(&Ps[w][g + 8][c]) = make_uint2(f2tf(pz), f2tf(pw));
        }
        ps0 += __shfl_xor_sync(0xffffffffu, ps0, 1);
        ps0 += __shfl_xor_sync(0xffffffffu, ps0, 2);
        ps1 += __shfl_xor_sync(0xffffffffu, ps1, 1);
        ps1 += __shfl_xor_sync(0xffffffffu, ps1, 2);

        l0 = l0 * al0 + ps0;
        l1 = l1 * al1 + ps1;
        m0v = mn0;
        m1v = mn1;
        #pragma unroll
        for (int nt = 0; nt < 8; nt++) {
            o[nt].x *= al0; o[nt].y *= al0;
            o[nt].z *= al1; o[nt].w *= al1;
        }
        __syncwarp();

        // P fragments (A operand of PV)
        uint32_t pf[4][4];
        #pragma unroll
        for (int ks = 0; ks < 4; ks++) {
            const int kk = ks * 8;
            pf[ks][0] = Ps[w][g    ][kk + tig];
            pf[ks][1] = Ps[w][g + 8][kk + tig];
            pf[ks][2] = Ps[w][g    ][kk + tig + 4];
            pf[ks][3] = Ps[w][g + 8][kk + tig + 4];
        }
        // O += P @ V : 8 n-tiles (64 dims) x 4 k-steps (32 kv)
        #pragma unroll
        for (int nt = 0; nt < 8; nt++) {
            const int d = nt * 8 + g;
            #pragma unroll
            for (int ks = 0; ks < 4; ks++) {
                const uint32_t b0 = Vt[VT_IDX(d, ks * 8 + tig)];
                const uint32_t b1 = Vt[VT_IDX(d, ks * 8 + tig + 4)];
                mma_tf32(o[nt], pf[ks], b0, b1);
            }
        }
        __syncthreads();
    }

    const float inv0 = 1.0f / l0;
    const float inv1 = 1.0f / l1;
    #pragma unroll
    for (int nt = 0; nt < 8; nt++) {
        const int col = h * HEAD_DIM + nt * 8 + 2 * tig;
        *reinterpret_cast<float2*>(&g_O[(size_t)r0 * D_MODEL + col]) =
            make_float2(o[nt].x * inv0, o[nt].y * inv0);
        *reinterpret_cast<float2*>(&g_O[(size_t)r1 * D_MODEL + col]) =
            make_float2(o[nt].z * inv1, o[nt].w * inv1);
    }
}

// ---------------------------------------------------------------------------
// Launch
// ---------------------------------------------------------------------------
extern "C" void kernel_launch(void* const* d_in, const int* in_sizes, int n_in,
                              void* d_out, int out_size)
{
    (void)in_sizes; (void)n_in; (void)out_size;
    const float* x  = (const float*)d_in[0];
    const float* Wq = (const float*)d_in[1];
    const float* Wk = (const float*)d_in[2];
    const float* Wv = (const float*)d_in[3];
    const float* Wo = (const float*)d_in[4];
    float* out = (float*)d_out;

    dim3 gproj(D_MODEL / 128, T_SEQ / 128, 3);
    qkv_gemm_tc<<<gproj, 256>>>(x, Wq, Wk, Wv);

    dim3 gattn(T_SEQ / 64, NUM_HEADS);
    flash_attn_tc<<<gattn, 128>>>();

    dim3 gout(D_MODEL / 128, T_SEQ / 128, 1);
    out_gemm_tc<<<gout, 256>>>(Wo, out);
}

// round 4
// speedup vs baseline: 6.2216x; 1.1693x over previous
#include <cuda_runtime.h>
#include <cstdint>

#define T_SEQ     4096
#define D_MODEL   1024
#define NUM_HEADS 16
#define HEAD_DIM  64

// Q pre-scale: (1/sqrt(64)) * log2(e)  -> softmax done in base-2 domain
#define QSCALE 0.18033688011112042f

// Scratch. g_Q/g_K/g_V hold tf32-bit patterns (as float), g_O raw fp32.
__device__ float g_Q[T_SEQ * D_MODEL];
__device__ float g_K[T_SEQ * D_MODEL];
__device__ float g_V[T_SEQ * D_MODEL];
__device__ float g_O[T_SEQ * D_MODEL];

// ---------------------------------------------------------------------------
// helpers
// ---------------------------------------------------------------------------
__device__ __forceinline__ uint32_t f2tf(float f) {
    uint32_t u;
    asm("cvt.rna.tf32.f32 %0, %1;" : "=r"(u) : "f"(f));
    return u;
}
__device__ __forceinline__ float fexp2(float x) {
    float y;
    asm("ex2.approx.ftz.f32 %0, %1;" : "=f"(y) : "f"(x));
    return y;
}
__device__ __forceinline__ void mma_tf32(float4& c, const uint32_t a[4],
                                         uint32_t b0, uint32_t b1) {
    asm volatile(
        "mma.sync.aligned.m16n8k8.row.col.f32.tf32.tf32.f32 "
        "{%0,%1,%2,%3}, {%4,%5,%6,%7}, {%8,%9}, {%10,%11,%12,%13};\n"
        : "=f"(c.x), "=f"(c.y), "=f"(c.z), "=f"(c.w)
        : "r"(a[0]), "r"(a[1]), "r"(a[2]), "r"(a[3]),
          "r"(b0), "r"(b1),
          "f"(c.x), "f"(c.y), "f"(c.z), "f"(c.w));
}
__device__ __forceinline__ void cp16(void* smem, const void* gmem) {
    uint32_t s = (uint32_t)__cvta_generic_to_shared(smem);
    asm volatile("cp.async.cg.shared.global [%0], [%1], 16;\n" :: "r"(s), "l"(gmem));
}
#define CP_COMMIT() asm volatile("cp.async.commit_group;\n" ::: "memory")
#define CP_WAIT0()  asm volatile("cp.async.wait_group 0;\n" ::: "memory")

// ---------------------------------------------------------------------------
// tf32 GEMM: C[M,N] = A[M,K] @ B[N,K]^T, cp.async double-buffered.
// 256 thr = 8 warps (2m x 4n), BM=BN=128, BK=32. Raw fp32 in smem [row][k]
// pad 36 (frag reads bank 4g+tig: conflict-free); cvt to tf32 at frag load.
// mode: 0 = raw fp32 store, 1 = tf32 store, 2 = scale+tf32 store.
// ---------------------------------------------------------------------------
#define GS_TILE (128 * 36)

__device__ __forceinline__ void gemm_body(
    const float* __restrict__ A, const float* __restrict__ B,
    float* __restrict__ C, int M, int N, int K, int mode, float scl)
{
    extern __shared__ float gsm[];
    float* As = gsm;                 // [2][128][36]
    float* Bs = gsm + 2 * GS_TILE;   // [2][128][36]

    const int tid  = threadIdx.x;
    const int lane = tid & 31;
    const int wid  = tid >> 5;
    const int g    = lane >> 2;
    const int tig  = lane & 3;
    const int wm   = wid >> 2;
    const int wn   = wid & 3;
    const int m0   = blockIdx.y * 128;
    const int n0   = blockIdx.x * 128;
    const int mb   = wm * 64;
    const int nb   = wn * 32;

    float4 acc[4][4];
    #pragma unroll
    for (int i = 0; i < 4; i++)
        #pragma unroll
        for (int j = 0; j < 4; j++) acc[i][j] = make_float4(0.f, 0.f, 0.f, 0.f);

    const int n_it = K / 32;

    auto issue = [&](int it, int st) {
        const int k0 = it * 32;
        float* Ad = As + st * GS_TILE;
        float* Bd = Bs + st * GS_TILE;
        #pragma unroll
        for (int i = 0; i < 4; i++) {
            const int id  = tid + i * 256;
            const int row = id >> 3;
            const int k4  = (id & 7) * 4;
            cp16(&Ad[row * 36 + k4], &A[(size_t)(m0 + row) * K + k0 + k4]);
            cp16(&Bd[row * 36 + k4], &B[(size_t)(n0 + row) * K + k0 + k4]);
        }
    };

    issue(0, 0);
    CP_COMMIT();

    for (int it = 0; it < n_it; it++) {
        CP_WAIT0();
        __syncthreads();
        if (it + 1 < n_it) {
            issue(it + 1, (it + 1) & 1);
            CP_COMMIT();
        }
        const float* Ac = As + (it & 1) * GS_TILE;
        const float* Bc = Bs + (it & 1) * GS_TILE;

        #pragma unroll
        for (int ks = 0; ks < 4; ks++) {
            const int kk = ks * 8;
            uint32_t af[4][4], bf[4][2];
            #pragma unroll
            for (int mt = 0; mt < 4; mt++) {
                const int m = mb + mt * 16;
                af[mt][0] = f2tf(Ac[(m + g    ) * 36 + kk + tig]);
                af[mt][1] = f2tf(Ac[(m + g + 8) * 36 + kk + tig]);
                af[mt][2] = f2tf(Ac[(m + g    ) * 36 + kk + tig + 4]);
                af[mt][3] = f2tf(Ac[(m + g + 8) * 36 + kk + tig + 4]);
            }
            #pragma unroll
            for (int nt = 0; nt < 4; nt++) {
                const int n = nb + nt * 8 + g;
                bf[nt][0] = f2tf(Bc[n * 36 + kk + tig]);
                bf[nt][1] = f2tf(Bc[n * 36 + kk + tig + 4]);
            }
            #pragma unroll
            for (int mt = 0; mt < 4; mt++)
                #pragma unroll
                for (int nt = 0; nt < 4; nt++)
                    mma_tf32(acc[mt][nt], af[mt], bf[nt][0], bf[nt][1]);
        }
        __syncthreads();
    }

    #pragma unroll
    for (int mt = 0; mt < 4; mt++) {
        const int row0 = m0 + mb + mt * 16 + g;
        #pragma unroll
        for (int nt = 0; nt < 4; nt++) {
            const int col = n0 + nb + nt * 8 + 2 * tig;
            float vx = acc[mt][nt].x * scl, vy = acc[mt][nt].y * scl;
            float vz = acc[mt][nt].z * scl, vw = acc[mt][nt].w * scl;
            if (mode != 0) {
                vx = __uint_as_float(f2tf(vx)); vy = __uint_as_float(f2tf(vy));
                vz = __uint_as_float(f2tf(vz)); vw = __uint_as_float(f2tf(vw));
            }
            *reinterpret_cast<float2*>(&C[(size_t)row0 * N + col]) = make_float2(vx, vy);
            *reinterpret_cast<float2*>(&C[(size_t)(row0 + 8) * N + col]) = make_float2(vz, vw);
        }
    }
}

__global__ __launch_bounds__(256) void qkv_gemm_tc(
    const float* __restrict__ x,
    const float* __restrict__ Wq,
    const float* __restrict__ Wk,
    const float* __restrict__ Wv)
{
    const float* B = (blockIdx.z == 0) ? Wq : (blockIdx.z == 1) ? Wk : Wv;
    float*       C = (blockIdx.z == 0) ? g_Q : (blockIdx.z == 1) ? g_K : g_V;
    const int   md = (blockIdx.z == 0) ? 2 : 1;
    const float sc = (blockIdx.z == 0) ? QSCALE : 1.0f;
    gemm_body(x, B, C, T_SEQ, D_MODEL, D_MODEL, md, sc);
}

__global__ __launch_bounds__(256) void out_gemm_tc(
    const float* __restrict__ Wo, float* __restrict__ out)
{
    gemm_body(g_O, Wo, out, T_SEQ, D_MODEL, D_MODEL, 0, 1.0f);
}

// ---------------------------------------------------------------------------
// Causal flash attention, tf32, cp.async double-buffered.
// 256 thr = 8 warps, BQ=128 (16 rows/warp), KV tiles BS=64.
// K,V smem [s][d] pad 68:
//   S b-frag  (row n=8nt+g, col 8ks+tig): bank 4g+tig   -> conflict-free
//   PV b-frag (row 8ks+tig, col 8nt+g):   bank 4tig+g   -> conflict-free
// Ps per-warp [16][68] (stride 68: frag reads bank (4g+tig)%32 conflict-free;
// round-2 stride 36 overflowed when BS went 32->64 -> the round-3 crash).
// Q (pre-scaled, tf32) register-resident. Softmax in log2 domain (ex2).
// Interior tiles unmasked; last 2 tiles masked; fully-masked warps skip.
// ---------------------------------------------------------------------------
#define FKV      (64 * 68)
#define PS_WARP  (16 * 68)

__global__ __launch_bounds__(256) void flash_attn_tc2()
{
    extern __shared__ uint32_t fsm[];
    // [stage][K|V][64][68], then Ps[8][16][68]
    uint32_t* Psw_base = fsm + 4 * FKV;

    const int tid  = threadIdx.x;
    const int lane = tid & 31;
    const int w    = tid >> 5;
    const int g    = lane >> 2;
    const int tig  = lane & 3;
    const int bq   = (int)gridDim.x - 1 - (int)blockIdx.x;  // heavy first
    const int h    = blockIdx.y;
    const int q0   = bq * 128;
    const int r0   = q0 + w * 16 + g;
    const int r1   = r0 + 8;

    // Q fragments (tf32 bits, pre-scaled by QSCALE)
    uint32_t qf[8][4];
    {
        const uint32_t* Qb = reinterpret_cast<const uint32_t*>(g_Q);
        const size_t b0 = (size_t)r0 * D_MODEL + h * HEAD_DIM;
        const size_t b1 = (size_t)r1 * D_MODEL + h * HEAD_DIM;
        #pragma unroll
        for (int ks = 0; ks < 8; ks++) {
            qf[ks][0] = Qb[b0 + ks * 8 + tig];
            qf[ks][1] = Qb[b1 + ks * 8 + tig];
            qf[ks][2] = Qb[b0 + ks * 8 + tig + 4];
            qf[ks][3] = Qb[b1 + ks * 8 + tig + 4];
        }
    }

    float mr0 = -1e30f, mr1 = -1e30f, l0 = 0.f, l1 = 0.f;
    float4 o[8];
    #pragma unroll
    for (int i = 0; i < 8; i++) o[i] = make_float4(0.f, 0.f, 0.f, 0.f);

    const int ntiles = 2 * bq + 2;

    auto issue = [&](int jt, int st) {
        const int j0 = jt * 64;
        uint32_t* Kd = fsm + st * 2 * FKV;
        uint32_t* Vd = Kd + FKV;
        #pragma unroll
        for (int i = 0; i < 4; i++) {
            const int id = tid + i * 256;
            const int s  = id >> 4;
            const int c4 = (id & 15) * 4;
            const size_t go = (size_t)(j0 + s) * D_MODEL + h * HEAD_DIM + c4;
            cp16(&Kd[s * 68 + c4], &g_K[go]);
            cp16(&Vd[s * 68 + c4], &g_V[go]);
        }
    };

    issue(0, 0);
    CP_COMMIT();

    for (int jt = 0; jt < ntiles; jt++) {
        CP_WAIT0();
        __syncthreads();
        if (jt + 1 < ntiles) {
            issue(jt + 1, (jt + 1) & 1);
            CP_COMMIT();
        }
        const uint32_t* Kt = fsm + (jt & 1) * 2 * FKV;
        const uint32_t* Vt = Kt + FKV;
        const int j0     = jt * 64;
        const bool masked = (jt >= 2 * bq);

        if (masked && j0 > q0 + w * 16 + 15) continue;  // warp fully masked

        // S = Q K^T : 16 x 64 per warp
        float4 sa[8];
        #pragma unroll
        for (int nt = 0; nt < 8; nt++) sa[nt] = make_float4(0.f, 0.f, 0.f, 0.f);
        #pragma unroll
        for (int ks = 0; ks < 8; ks++) {
            #pragma unroll
            for (int nt = 0; nt < 8; nt++) {
                const int n = nt * 8 + g;
                const uint32_t b0 = Kt[n * 68 + ks * 8 + tig];
                const uint32_t b1 = Kt[n * 68 + ks * 8 + tig + 4];
                mma_tf32(sa[nt], qf[ks], b0, b1);
            }
        }

        if (masked) {
            #pragma unroll
            for (int nt = 0; nt < 8; nt++) {
                const int c0 = j0 + nt * 8 + 2 * tig;
                if (c0     > r0) sa[nt].x = -1e30f;
                if (c0 + 1 > r0) sa[nt].y = -1e30f;
                if (c0     > r1) sa[nt].z = -1e30f;
                if (c0 + 1 > r1) sa[nt].w = -1e30f;
            }
        }

        float mx0 = -1e30f, mx1 = -1e30f;
        #pragma unroll
        for (int nt = 0; nt < 8; nt++) {
            mx0 = fmaxf(mx0, fmaxf(sa[nt].x, sa[nt].y));
            mx1 = fmaxf(mx1, fmaxf(sa[nt].z, sa[nt].w));
        }
        mx0 = fmaxf(mx0, __shfl_xor_sync(0xffffffffu, mx0, 1));
        mx0 = fmaxf(mx0, __shfl_xor_sync(0xffffffffu, mx0, 2));
        mx1 = fmaxf(mx1, __shfl_xor_sync(0xffffffffu, mx1, 1));
        mx1 = fmaxf(mx1, __shfl_xor_sync(0xffffffffu, mx1, 2));

        const float mn0 = fmaxf(mr0, mx0);
        const float mn1 = fmaxf(mr1, mx1);
        const float al0 = fexp2(mr0 - mn0);
        const float al1 = fexp2(mr1 - mn1);

        uint32_t* Psw = Psw_base + w * PS_WARP;
        float ps0 = 0.f, ps1 = 0.f;
        #pragma unroll
        for (int nt = 0; nt < 8; nt++) {
            const float px = fexp2(sa[nt].x - mn0);
            const float py = fexp2(sa[nt].y - mn0);
            const float pz = fexp2(sa[nt].z - mn1);
            const float pw = fexp2(sa[nt].w - mn1);
            ps0 += px + py;
            ps1 += pz + pw;
            const int c = nt * 8 + 2 * tig;
            *reinterpret_cast<uint2*>(&Psw[g * 68 + c]) =
                make_uint2(f2tf(px), f2tf(py));
            *reinterpret_cast<uint2*>(&Psw[(g + 8) * 68 + c]) =
                make_uint2(f2tf(pz), f2tf(pw));
        }
        ps0 += __shfl_xor_sync(0xffffffffu, ps0, 1);
        ps0 += __shfl_xor_sync(0xffffffffu, ps0, 2);
        ps1 += __shfl_xor_sync(0xffffffffu, ps1, 1);
        ps1 += __shfl_xor_sync(0xffffffffu, ps1, 2);

        l0 = l0 * al0 + ps0;
        l1 = l1 * al1 + ps1;
        mr0 = mn0;
        mr1 = mn1;
        #pragma unroll
        for (int nt = 0; nt < 8; nt++) {
            o[nt].x *= al0; o[nt].y *= al0;
            o[nt].z *= al1; o[nt].w *= al1;
        }
        __syncwarp();

        // O += P @ V : P 16x64, V 64x64
        #pragma unroll
        for (int ks = 0; ks < 8; ks++) {
            uint32_t pf[4];
            pf[0] = Psw[ g      * 68 + ks * 8 + tig];
            pf[1] = Psw[(g + 8) * 68 + ks * 8 + tig];
            pf[2] = Psw[ g      * 68 + ks * 8 + tig + 4];
            pf[3] = Psw[(g + 8) * 68 + ks * 8 + tig + 4];
            #pragma unroll
            for (int nt = 0; nt < 8; nt++) {
                const int d = nt * 8 + g;
                const uint32_t b0 = Vt[(ks * 8 + tig    ) * 68 + d];
                const uint32_t b1 = Vt[(ks * 8 + tig + 4) * 68 + d];
                mma_tf32(o[nt], pf, b0, b1);
            }
        }
        __syncwarp();
    }

    const float inv0 = 1.0f / l0;
    const float inv1 = 1.0f / l1;
    #pragma unroll
    for (int nt = 0; nt < 8; nt++) {
        const int col = h * HEAD_DIM + nt * 8 + 2 * tig;
        *reinterpret_cast<float2*>(&g_O[(size_t)r0 * D_MODEL + col]) =
            make_float2(o[nt].x * inv0, o[nt].y * inv0);
        *reinterpret_cast<float2*>(&g_O[(size_t)r1 * D_MODEL + col]) =
            make_float2(o[nt].z * inv1, o[nt].w * inv1);
    }
}

// ---------------------------------------------------------------------------
// Launch
// ---------------------------------------------------------------------------
#define GEMM_SMEM  (4 * GS_TILE * 4)                 // 73,728 B
#define FLASH_SMEM ((4 * FKV + 8 * PS_WARP) * 4)     // 104,448 B

extern "C" void kernel_launch(void* const* d_in, const int* in_sizes, int n_in,
                              void* d_out, int out_size)
{
    (void)in_sizes; (void)n_in; (void)out_size;
    const float* x  = (const float*)d_in[0];
    const float* Wq = (const float*)d_in[1];
    const float* Wk = (const float*)d_in[2];
    const float* Wv = (const float*)d_in[3];
    const float* Wo = (const float*)d_in[4];
    float* out = (float*)d_out;

    cudaFuncSetAttribute(qkv_gemm_tc,
        cudaFuncAttributeMaxDynamicSharedMemorySize, GEMM_SMEM);
    cudaFuncSetAttribute(out_gemm_tc,
        cudaFuncAttributeMaxDynamicSharedMemorySize, GEMM_SMEM);
    cudaFuncSetAttribute(flash_attn_tc2,
        cudaFuncAttributeMaxDynamicSharedMemorySize, FLASH_SMEM);

    dim3 gproj(D_MODEL / 128, T_SEQ / 128, 3);
    qkv_gemm_tc<<<gproj, 256, GEMM_SMEM>>>(x, Wq, Wk, Wv);

    dim3 gattn(T_SEQ / 128, NUM_HEADS);
    flash_attn_tc2<<<gattn, 256, FLASH_SMEM>>>();

    dim3 gout(D_MODEL / 128, T_SEQ / 128, 1);
    out_gemm_tc<<<gout, 256, GEMM_SMEM>>>(Wo, out);
}

// round 5
// speedup vs baseline: 6.3386x; 1.0188x over previous
#include <cuda_runtime.h>
#include <cstdint>

#define T_SEQ     4096
#define D_MODEL   1024
#define NUM_HEADS 16
#define HEAD_DIM  64

// Q pre-scale: (1/sqrt(64)) * log2(e)  -> softmax done in base-2 domain
#define QSCALE 0.18033688011112042f

// Scratch. g_Q/g_K/g_V/g_O hold tf32-bit patterns (as float).
__device__ float g_Q[T_SEQ * D_MODEL];
__device__ float g_K[T_SEQ * D_MODEL];
__device__ float g_V[T_SEQ * D_MODEL];
__device__ float g_O[T_SEQ * D_MODEL];
// tf32-converted inputs: x at 0, Wq/Wk/Wv/Wo at 4M + i*1M
#define XW_X  0
#define XW_WQ (4 * 1024 * 1024)
#define XW_WK (5 * 1024 * 1024)
#define XW_WV (6 * 1024 * 1024)
#define XW_WO (7 * 1024 * 1024)
__device__ float g_TF[8 * 1024 * 1024];

// ---------------------------------------------------------------------------
// helpers
// ---------------------------------------------------------------------------
__device__ __forceinline__ uint32_t f2tf(float f) {
    uint32_t u;
    asm("cvt.rna.tf32.f32 %0, %1;" : "=r"(u) : "f"(f));
    return u;
}
__device__ __forceinline__ float fexp2(float x) {
    float y;
    asm("ex2.approx.ftz.f32 %0, %1;" : "=f"(y) : "f"(x));
    return y;
}
__device__ __forceinline__ void mma_tf32(float4& c, const uint32_t a[4],
                                         uint32_t b0, uint32_t b1) {
    asm volatile(
        "mma.sync.aligned.m16n8k8.row.col.f32.tf32.tf32.f32 "
        "{%0,%1,%2,%3}, {%4,%5,%6,%7}, {%8,%9}, {%10,%11,%12,%13};\n"
        : "=f"(c.x), "=f"(c.y), "=f"(c.z), "=f"(c.w)
        : "r"(a[0]), "r"(a[1]), "r"(a[2]), "r"(a[3]),
          "r"(b0), "r"(b1),
          "f"(c.x), "f"(c.y), "f"(c.z), "f"(c.w));
}
__device__ __forceinline__ void cp16(void* smem, const void* gmem) {
    uint32_t s = (uint32_t)__cvta_generic_to_shared(smem);
    asm volatile("cp.async.cg.shared.global [%0], [%1], 16;\n" :: "r"(s), "l"(gmem));
}
#define CP_COMMIT() asm volatile("cp.async.commit_group;\n" ::: "memory")
#define CP_WAIT0()  asm volatile("cp.async.wait_group 0;\n" ::: "memory")

// ---------------------------------------------------------------------------
// One-shot tf32 conversion of x + weights into g_TF.
// Segments (float4 units): x [0, 1M), Wq [1M, 1.25M), Wk, Wv, Wo.
// ---------------------------------------------------------------------------
__global__ __launch_bounds__(256) void cvt_inputs(
    const float* __restrict__ x,  const float* __restrict__ Wq,
    const float* __restrict__ Wk, const float* __restrict__ Wv,
    const float* __restrict__ Wo)
{
    const int i4 = blockIdx.x * blockDim.x + threadIdx.x;   // float4 index
    const float* src;
    int base;
    if (i4 < (1 << 20))            { src = x;  base = 0; }
    else if (i4 < (5 << 18))       { src = Wq; base = 1 << 20; }
    else if (i4 < (6 << 18))       { src = Wk; base = 5 << 18; }
    else if (i4 < (7 << 18))       { src = Wv; base = 6 << 18; }
    else                           { src = Wo; base = 7 << 18; }
    const float4 v = reinterpret_cast<const float4*>(src)[i4 - base];
    uint4 o = make_uint4(f2tf(v.x), f2tf(v.y), f2tf(v.z), f2tf(v.w));
    reinterpret_cast<uint4*>(g_TF)[i4] = o;
}

// ---------------------------------------------------------------------------
// tf32 GEMM: C[M,N] = A[M,K] @ B[N,K]^T. A,B already tf32 bit patterns.
// 256 thr = 8 warps (2m x 4n), BM=BN=128, BK=32, cp.async double-buffered,
// single __syncthreads per iteration. Smem [row][k] pad 36 (frag bank 4g+tig,
// conflict-free). mode: 0 raw fp32 store, 1 tf32 store, 2 scale+tf32 store.
// ---------------------------------------------------------------------------
#define GS_TILE (128 * 36)

__device__ __forceinline__ void gemm_body(
    const float* __restrict__ A, const float* __restrict__ B,
    float* __restrict__ C, int N, int K, int mode, float scl)
{
    extern __shared__ float gsm[];
    float* As = gsm;                 // [2][128][36]
    float* Bs = gsm + 2 * GS_TILE;   // [2][128][36]

    const int tid  = threadIdx.x;
    const int lane = tid & 31;
    const int wid  = tid >> 5;
    const int g    = lane >> 2;
    const int tig  = lane & 3;
    const int wm   = wid >> 2;
    const int wn   = wid & 3;
    const int m0   = blockIdx.y * 128;
    const int n0   = blockIdx.x * 128;
    const int mb   = wm * 64;
    const int nb   = wn * 32;

    float4 acc[4][4];
    #pragma unroll
    for (int i = 0; i < 4; i++)
        #pragma unroll
        for (int j = 0; j < 4; j++) acc[i][j] = make_float4(0.f, 0.f, 0.f, 0.f);

    const int n_it = K / 32;

    auto issue = [&](int it, int st) {
        const int k0 = it * 32;
        float* Ad = As + st * GS_TILE;
        float* Bd = Bs + st * GS_TILE;
        #pragma unroll
        for (int i = 0; i < 4; i++) {
            const int id  = tid + i * 256;
            const int row = id >> 3;
            const int k4  = (id & 7) * 4;
            cp16(&Ad[row * 36 + k4], &A[(size_t)(m0 + row) * K + k0 + k4]);
            cp16(&Bd[row * 36 + k4], &B[(size_t)(n0 + row) * K + k0 + k4]);
        }
    };

    issue(0, 0);
    CP_COMMIT();

    for (int it = 0; it < n_it; it++) {
        CP_WAIT0();
        __syncthreads();   // stage `it` visible; all warps done reading stage it&1 from it-1's view
        if (it + 1 < n_it) {
            issue(it + 1, (it + 1) & 1);
            CP_COMMIT();
        }
        const uint32_t* Ac = reinterpret_cast<const uint32_t*>(As + (it & 1) * GS_TILE);
        const uint32_t* Bc = reinterpret_cast<const uint32_t*>(Bs + (it & 1) * GS_TILE);

        #pragma unroll
        for (int ks = 0; ks < 4; ks++) {
            const int kk = ks * 8;
            uint32_t af[4][4], bf[4][2];
            #pragma unroll
            for (int mt = 0; mt < 4; mt++) {
                const int m = mb + mt * 16;
                af[mt][0] = Ac[(m + g    ) * 36 + kk + tig];
                af[mt][1] = Ac[(m + g + 8) * 36 + kk + tig];
                af[mt][2] = Ac[(m + g    ) * 36 + kk + tig + 4];
                af[mt][3] = Ac[(m + g + 8) * 36 + kk + tig + 4];
            }
            #pragma unroll
            for (int nt = 0; nt < 4; nt++) {
                const int n = nb + nt * 8 + g;
                bf[nt][0] = Bc[n * 36 + kk + tig];
                bf[nt][1] = Bc[n * 36 + kk + tig + 4];
            }
            #pragma unroll
            for (int mt = 0; mt < 4; mt++)
                #pragma unroll
                for (int nt = 0; nt < 4; nt++)
                    mma_tf32(acc[mt][nt], af[mt], bf[nt][0], bf[nt][1]);
        }
    }

    #pragma unroll
    for (int mt = 0; mt < 4; mt++) {
        const int row0 = m0 + mb + mt * 16 + g;
        #pragma unroll
        for (int nt = 0; nt < 4; nt++) {
            const int col = n0 + nb + nt * 8 + 2 * tig;
            float vx = acc[mt][nt].x * scl, vy = acc[mt][nt].y * scl;
            float vz = acc[mt][nt].z * scl, vw = acc[mt][nt].w * scl;
            if (mode != 0) {
                vx = __uint_as_float(f2tf(vx)); vy = __uint_as_float(f2tf(vy));
                vz = __uint_as_float(f2tf(vz)); vw = __uint_as_float(f2tf(vw));
            }
            *reinterpret_cast<float2*>(&C[(size_t)row0 * N + col]) = make_float2(vx, vy);
            *reinterpret_cast<float2*>(&C[(size_t)(row0 + 8) * N + col]) = make_float2(vz, vw);
        }
    }
}

__global__ __launch_bounds__(256, 2) void qkv_gemm_tc()
{
    const float* B = (blockIdx.z == 0) ? g_TF + XW_WQ
                   : (blockIdx.z == 1) ? g_TF + XW_WK : g_TF + XW_WV;
    float*       C = (blockIdx.z == 0) ? g_Q : (blockIdx.z == 1) ? g_K : g_V;
    const int   md = (blockIdx.z == 0) ? 2 : 1;
    const float sc = (blockIdx.z == 0) ? QSCALE : 1.0f;
    gemm_body(g_TF + XW_X, B, C, D_MODEL, D_MODEL, md, sc);
}

__global__ __launch_bounds__(256, 2) void out_gemm_tc(float* __restrict__ out)
{
    gemm_body(g_O, g_TF + XW_WO, out, D_MODEL, D_MODEL, 0, 1.0f);
}

// ---------------------------------------------------------------------------
// Causal flash attention, tf32, cp.async double-buffered, no P smem.
// 256 thr = 8 warps, BQ=128 (16 rows/warp), KV tiles BS=64.
// K,V smem [s][d] stride 76 (== 12 mod 32):
//   S b-frag  bank = 12g + tig  -> 32 distinct, conflict-free
//   PV b-frag bank = 12tig + g  -> 32 distinct, conflict-free
// P re-fragmented C->A via warp shuffles (no smem round-trip): owner of
// P[g][c] is lane (g<<2)|((c&7)>>1), comp (c&1 ? y|w : x|z). Target A-frag
// col 8ks+tig -> src lane (g<<2)|(tig>>1); col+4 -> src | 2.
// Softmax in log2 domain. Last 2 tiles masked; fully-masked warps skip.
// ---------------------------------------------------------------------------
#define FKV (64 * 76)

__global__ __launch_bounds__(256, 2) void flash_attn_tc2()
{
    extern __shared__ uint32_t fsm[];   // [stage][K|V][64][76]

    const int tid  = threadIdx.x;
    const int lane = tid & 31;
    const int w    = tid >> 5;
    const int g    = lane >> 2;
    const int tig  = lane & 3;
    const int bq   = (int)gridDim.x - 1 - (int)blockIdx.x;  // heavy first
    const int h    = blockIdx.y;
    const int q0   = bq * 128;
    const int r0   = q0 + w * 16 + g;
    const int r1   = r0 + 8;

    // Q fragments (tf32 bits, pre-scaled by QSCALE)
    uint32_t qf[8][4];
    {
        const uint32_t* Qb = reinterpret_cast<const uint32_t*>(g_Q);
        const size_t b0 = (size_t)r0 * D_MODEL + h * HEAD_DIM;
        const size_t b1 = (size_t)r1 * D_MODEL + h * HEAD_DIM;
        #pragma unroll
        for (int ks = 0; ks < 8; ks++) {
            qf[ks][0] = Qb[b0 + ks * 8 + tig];
            qf[ks][1] = Qb[b1 + ks * 8 + tig];
            qf[ks][2] = Qb[b0 + ks * 8 + tig + 4];
            qf[ks][3] = Qb[b1 + ks * 8 + tig + 4];
        }
    }

    float mr0 = -1e30f, mr1 = -1e30f, l0 = 0.f, l1 = 0.f;
    float4 o[8];
    #pragma unroll
    for (int i = 0; i < 8; i++) o[i] = make_float4(0.f, 0.f, 0.f, 0.f);

    const int ntiles = 2 * bq + 2;

    auto issue = [&](int jt, int st) {
        const int j0 = jt * 64;
        uint32_t* Kd = fsm + st * 2 * FKV;
        uint32_t* Vd = Kd + FKV;
        #pragma unroll
        for (int i = 0; i < 4; i++) {
            const int id = tid + i * 256;
            const int s  = id >> 4;
            const int c4 = (id & 15) * 4;
            const size_t go = (size_t)(j0 + s) * D_MODEL + h * HEAD_DIM + c4;
            cp16(&Kd[s * 76 + c4], &g_K[go]);
            cp16(&Vd[s * 76 + c4], &g_V[go]);
        }
    };

    issue(0, 0);
    CP_COMMIT();

    for (int jt = 0; jt < ntiles; jt++) {
        CP_WAIT0();
        __syncthreads();
        if (jt + 1 < ntiles) {
            issue(jt + 1, (jt + 1) & 1);
            CP_COMMIT();
        }
        const uint32_t* Kt = fsm + (jt & 1) * 2 * FKV;
        const uint32_t* Vt = Kt + FKV;
        const int j0      = jt * 64;
        const bool masked = (jt >= 2 * bq);

        if (masked && j0 > q0 + w * 16 + 15) continue;  // warp fully masked

        // S = Q K^T : 16 x 64 per warp
        float4 sa[8];
        #pragma unroll
        for (int nt = 0; nt < 8; nt++) sa[nt] = make_float4(0.f, 0.f, 0.f, 0.f);
        #pragma unroll
        for (int ks = 0; ks < 8; ks++) {
            #pragma unroll
            for (int nt = 0; nt < 8; nt++) {
                const int n = nt * 8 + g;
                const uint32_t b0 = Kt[n * 76 + ks * 8 + tig];
                const uint32_t b1 = Kt[n * 76 + ks * 8 + tig + 4];
                mma_tf32(sa[nt], qf[ks], b0, b1);
            }
        }

        if (masked) {
            #pragma unroll
            for (int nt = 0; nt < 8; nt++) {
                const int c0 = j0 + nt * 8 + 2 * tig;
                if (c0     > r0) sa[nt].x = -1e30f;
                if (c0 + 1 > r0) sa[nt].y = -1e30f;
                if (c0     > r1) sa[nt].z = -1e30f;
                if (c0 + 1 > r1) sa[nt].w = -1e30f;
            }
        }

        float mx0 = -1e30f, mx1 = -1e30f;
        #pragma unroll
        for (int nt = 0; nt < 8; nt++) {
            mx0 = fmaxf(mx0, fmaxf(sa[nt].x, sa[nt].y));
            mx1 = fmaxf(mx1, fmaxf(sa[nt].z, sa[nt].w));
        }
        mx0 = fmaxf(mx0, __shfl_xor_sync(0xffffffffu, mx0, 1));
        mx0 = fmaxf(mx0, __shfl_xor_sync(0xffffffffu, mx0, 2));
        mx1 = fmaxf(mx1, __shfl_xor_sync(0xffffffffu, mx1, 1));
        mx1 = fmaxf(mx1, __shfl_xor_sync(0xffffffffu, mx1, 2));

        const float mn0 = fmaxf(mr0, mx0);
        const float mn1 = fmaxf(mr1, mx1);
        const float al0 = fexp2(mr0 - mn0);
        const float al1 = fexp2(mr1 - mn1);

        // exp2, row-sum, and write tf32-P bits back into sa (register reuse)
        float ps0 = 0.f, ps1 = 0.f;
        #pragma unroll
        for (int nt = 0; nt < 8; nt++) {
            const float px = fexp2(sa[nt].x - mn0);
            const float py = fexp2(sa[nt].y - mn0);
            const float pz = fexp2(sa[nt].z - mn1);
            const float pw = fexp2(sa[nt].w - mn1);
            ps0 += px + py;
            ps1 += pz + pw;
            sa[nt].x = __uint_as_float(f2tf(px));
            sa[nt].y = __uint_as_float(f2tf(py));
            sa[nt].z = __uint_as_float(f2tf(pz));
            sa[nt].w = __uint_as_float(f2tf(pw));
        }
        ps0 += __shfl_xor_sync(0xffffffffu, ps0, 1);
        ps0 += __shfl_xor_sync(0xffffffffu, ps0, 2);
        ps1 += __shfl_xor_sync(0xffffffffu, ps1, 1);
        ps1 += __shfl_xor_sync(0xffffffffu, ps1, 2);

        l0 = l0 * al0 + ps0;
        l1 = l1 * al1 + ps1;
        mr0 = mn0;
        mr1 = mn1;
        #pragma unroll
        for (int nt = 0; nt < 8; nt++) {
            o[nt].x *= al0; o[nt].y *= al0;
            o[nt].z *= al1; o[nt].w *= al1;
        }

        // O += P @ V : P re-fragmented via shuffles, V b-frags from smem
        const int s0 = (g << 2) | (tig >> 1);
        const int s1 = s0 | 2;
        const bool hi = (tig & 1);
        #pragma unroll
        for (int ks = 0; ks < 8; ks++) {
            const float ax0 = __shfl_sync(0xffffffffu, sa[ks].x, s0);
            const float ay0 = __shfl_sync(0xffffffffu, sa[ks].y, s0);
            const float az0 = __shfl_sync(0xffffffffu, sa[ks].z, s0);
            const float aw0 = __shfl_sync(0xffffffffu, sa[ks].w, s0);
            const float ax1 = __shfl_sync(0xffffffffu, sa[ks].x, s1);
            const float ay1 = __shfl_sync(0xffffffffu, sa[ks].y, s1);
            const float az1 = __shfl_sync(0xffffffffu, sa[ks].z, s1);
            const float aw1 = __shfl_sync(0xffffffffu, sa[ks].w, s1);
            uint32_t pf[4];
            pf[0] = __float_as_uint(hi ? ay0 : ax0);
            pf[1] = __float_as_uint(hi ? aw0 : az0);
            pf[2] = __float_as_uint(hi ? ay1 : ax1);
            pf[3] = __float_as_uint(hi ? aw1 : az1);
            #pragma unroll
            for (int nt = 0; nt < 8; nt++) {
                const int d = nt * 8 + g;
                const uint32_t b0 = Vt[(ks * 8 + tig    ) * 76 + d];
                const uint32_t b1 = Vt[(ks * 8 + tig + 4) * 76 + d];
                mma_tf32(o[nt], pf, b0, b1);
            }
        }
    }

    // epilogue: write O as tf32 bits (A operand of the out projection)
    const float inv0 = 1.0f / l0;
    const float inv1 = 1.0f / l1;
    #pragma unroll
    for (int nt = 0; nt < 8; nt++) {
        const int col = h * HEAD_DIM + nt * 8 + 2 * tig;
        uint2 lo = make_uint2(f2tf(o[nt].x * inv0), f2tf(o[nt].y * inv0));
        uint2 hi2 = make_uint2(f2tf(o[nt].z * inv1), f2tf(o[nt].w * inv1));
        *reinterpret_cast<uint2*>(&g_O[(size_t)r0 * D_MODEL + col]) = lo;
        *reinterpret_cast<uint2*>(&g_O[(size_t)r1 * D_MODEL + col]) = hi2;
    }
}

// ---------------------------------------------------------------------------
// Launch
// ---------------------------------------------------------------------------
#define GEMM_SMEM  (4 * GS_TILE * 4)    // 73,728 B
#define FLASH_SMEM (4 * FKV * 4)        // 77,824 B

extern "C" void kernel_launch(void* const* d_in, const int* in_sizes, int n_in,
                              void* d_out, int out_size)
{
    (void)in_sizes; (void)n_in; (void)out_size;
    const float* x  = (const float*)d_in[0];
    const float* Wq = (const float*)d_in[1];
    const float* Wk = (const float*)d_in[2];
    const float* Wv = (const float*)d_in[3];
    const float* Wo = (const float*)d_in[4];
    float* out = (float*)d_out;

    cudaFuncSetAttribute(qkv_gemm_tc,
        cudaFuncAttributeMaxDynamicSharedMemorySize, GEMM_SMEM);
    cudaFuncSetAttribute(out_gemm_tc,
        cudaFuncAttributeMaxDynamicSharedMemorySize, GEMM_SMEM);
    cudaFuncSetAttribute(flash_attn_tc2,
        cudaFuncAttributeMaxDynamicSharedMemorySize, FLASH_SMEM);

    cvt_inputs<<<8192, 256>>>(x, Wq, Wk, Wv, Wo);   // 2M float4

    dim3 gproj(D_MODEL / 128, T_SEQ / 128, 3);
    qkv_gemm_tc<<<gproj, 256, GEMM_SMEM>>>();

    dim3 gattn(T_SEQ / 128, NUM_HEADS);
    flash_attn_tc2<<<gattn, 256, FLASH_SMEM>>>();

    dim3 gout(D_MODEL / 128, T_SEQ / 128, 1);
    out_gemm_tc<<<gout, 256, GEMM_SMEM>>>(out);
}